// round 9
// baseline (speedup 1.0000x reference)
#include <cuda_runtime.h>
#include <cuda_bf16.h>
#include <cstdint>
#include <math.h>

#define BB 4096
#define FF 256

// ---------------- scratch (device globals) ----------------------------------
__device__ __nv_bfloat16 d_s_hi[BB*FF],  d_s_lo[BB*FF];
__device__ __nv_bfloat16 d_g_hi[BB*FF],  d_g_lo[BB*FF];
__device__ __nv_bfloat16 d_c_hi[BB*FF],  d_c_lo[BB*FF];
__device__ __nv_bfloat16 d_wp_hi[FF*FF], d_wp_lo[FF*FF];
__device__ __nv_bfloat16 d_wih_hi[3*FF*FF], d_wih_lo[3*FF*FF];
__device__ __nv_bfloat16 d_whh_hi[3*FF*FF], d_whh_lo[3*FF*FF];
__device__ float g_gh [BB*3*FF];
__device__ float g_gi0[BB*3*FF], g_gi1[BB*3*FF], g_gi2[BB*3*FF];
__device__ int   g_cnt[BB];

// ---------------- helpers ----------------------------------------------------
__device__ __forceinline__ uint32_t smem_u32(const void* p) {
    uint32_t a;
    asm("{ .reg .u64 t; cvta.to.shared.u64 t, %1; cvt.u32.u64 %0, t; }" : "=r"(a) : "l"(p));
    return a;
}
__device__ __forceinline__ void cp16(uint32_t dst, const void* src) {
    asm volatile("cp.async.cg.shared.global [%0], [%1], 16;" :: "r"(dst), "l"(src));
}
__device__ __forceinline__ void cp_commit() {
    asm volatile("cp.async.commit_group;" ::: "memory");
}
template<int n>
__device__ __forceinline__ void cp_wait() {
    asm volatile("cp.async.wait_group %0;" :: "n"(n) : "memory");
}
__device__ __forceinline__ void ldsm4(uint32_t* r, uint32_t addr) {
    asm volatile("ldmatrix.sync.aligned.m8n8.x4.shared.b16 {%0,%1,%2,%3}, [%4];"
        : "=r"(r[0]), "=r"(r[1]), "=r"(r[2]), "=r"(r[3]) : "r"(addr));
}
__device__ __forceinline__ void mma16816(float* d, const uint32_t* a, uint32_t b0, uint32_t b1) {
    asm volatile("mma.sync.aligned.m16n8k16.row.col.f32.bf16.bf16.f32 "
        "{%0,%1,%2,%3}, {%4,%5,%6,%7}, {%8,%9}, {%0,%1,%2,%3};"
        : "+f"(d[0]), "+f"(d[1]), "+f"(d[2]), "+f"(d[3])
        : "r"(a[0]), "r"(a[1]), "r"(a[2]), "r"(a[3]), "r"(b0), "r"(b1));
}
__device__ __forceinline__ void split_store(float v, __nv_bfloat16* hi, __nv_bfloat16* lo, size_t i) {
    __nv_bfloat16 h = __float2bfloat16(v);
    hi[i] = h;
    lo[i] = __float2bfloat16(v - __bfloat162float(h));
}

// ---------------- shared GEMM pipeline ---------------------------------------
// Block 128x128, 8 warps of 64x32, BK=64 chunks, 3-stage cp.async.
// SWEEP: chunk cn -> product p=cn>>2, kk=(cn&3)*64 (K'=768 sweep).
// !SWEEP: product fixed = pfix, kk = cn*64 (single K=256 product).
#define SROW 72
#define NSTAGE 3
#define STG_BYTES (128 * SROW * 2)          // 18432
#define STAGE_SZ  (2 * STG_BYTES)           // 36864
#define GSMEM     (NSTAGE * STAGE_SZ)       // 110592

template<int NCH, bool SWEEP>
__device__ __forceinline__ void run_gemm(
    const __nv_bfloat16* __restrict__ Ah, const __nv_bfloat16* __restrict__ Al,
    const __nv_bfloat16* __restrict__ Bh, const __nv_bfloat16* __restrict__ Bl,
    int pfix, int m0, int j0, uint32_t smem, float acc[4][4][4])
{
    int t = threadIdx.x, wid = t >> 5, lane = t & 31;
    int warp_m = wid & 1, warp_n = wid >> 1;
    int aRow  = warp_m * 64 + (lane & 15);
    int aColH = (lane >> 4) << 3;
    int bRow  = warp_n * 32 + lane;

    auto issue = [&](int cn, int st) {
        int p, kk;
        if (SWEEP) { p = cn >> 2; kk = (cn & 3) * 64; }
        else       { p = pfix;    kk = cn * 64; }
        const __nv_bfloat16* As = (p == 1) ? Al : Ah;
        const __nv_bfloat16* Bs = (p == 2) ? Bl : Bh;
        uint32_t dA = smem + st * STAGE_SZ;
        uint32_t dB = dA + STG_BYTES;
        #pragma unroll
        for (int k = 0; k < 4; k++) {
            int id = t + 256 * k;
            int r = id >> 3, q = id & 7;
            cp16(dA + (uint32_t)(r * SROW + q * 8) * 2,
                 As + (size_t)(m0 + r) * FF + kk + q * 8);
            cp16(dB + (uint32_t)(r * SROW + q * 8) * 2,
                 Bs + (size_t)(j0 + r) * FF + kk + q * 8);
        }
        cp_commit();
    };

    issue(0, 0); issue(1, 1);

    #pragma unroll 1
    for (int c = 0; c < NCH; c++) {
        if (c == NCH - 1) cp_wait<0>(); else cp_wait<1>();
        __syncthreads();
        if (c + 2 < NCH) issue(c + 2, (c + 2) % NSTAGE);

        uint32_t baseA = smem + (c % NSTAGE) * STAGE_SZ;
        uint32_t baseB = baseA + STG_BYTES;
        #pragma unroll
        for (int ks = 0; ks < 4; ks++) {
            uint32_t a[4][4];
            #pragma unroll
            for (int mi = 0; mi < 4; mi++)
                ldsm4(a[mi], baseA + (uint32_t)(((aRow + mi*16) * SROW + ks*16 + aColH) * 2));
            uint32_t bb0[4], bb1[4];
            ldsm4(bb0, baseB + (uint32_t)((bRow * SROW + ks*16 + 0) * 2));
            ldsm4(bb1, baseB + (uint32_t)((bRow * SROW + ks*16 + 8) * 2));
            #pragma unroll
            for (int mi = 0; mi < 4; mi++)
                #pragma unroll
                for (int ni = 0; ni < 4; ni++)
                    mma16816(acc[mi][ni], a[mi], bb0[ni], bb1[ni]);
        }
    }
}

// raw f32 tile store into [*, 768] buffer at column offset j0
__device__ __forceinline__ void epi_store_raw(float* __restrict__ out,
                                              int m0, int j0, float acc[4][4][4])
{
    int t = threadIdx.x, wid = t >> 5, lane = t & 31;
    int warp_m = wid & 1, warp_n = wid >> 1;
    int colBase = warp_n * 32 + (lane & 3) * 2;
    int rowBase = m0 + warp_m * 64 + (lane >> 2);
    #pragma unroll
    for (int mi = 0; mi < 4; mi++)
        #pragma unroll
        for (int ni = 0; ni < 4; ni++) {
            int col = colBase + ni * 8;
            #pragma unroll
            for (int half = 0; half < 2; half++) {
                int row = rowBase + mi * 16 + half * 8;
                *(float2*)(out + (size_t)row * (3*FF) + j0 + col) =
                    make_float2(acc[mi][ni][half*2], acc[mi][ni][half*2+1]);
            }
        }
}

// ---------------- kernel P: bf16 hi/lo prep for weights + g ------------------
__global__ __launch_bounds__(256) void prep(const float* __restrict__ Wp,
                                            const float* __restrict__ Wih,
                                            const float* __restrict__ Whh,
                                            const float* __restrict__ g)
{
    int i = blockIdx.x * 256 + threadIdx.x;
    if (i < FF*FF)      split_store(Wp[i],  d_wp_hi,  d_wp_lo,  i);
    if (i < 3*FF*FF) {  split_store(Wih[i], d_wih_hi, d_wih_lo, i);
                        split_store(Whh[i], d_whh_hi, d_whh_lo, i); }
    if (i < BB*FF)      split_store(g[i],   d_g_hi,   d_g_lo,   i);
}

// ---------------- fused: gh GEMM (blocks 0..191) + attn pool (rest) ----------
#define GH_BLOCKS 192

__global__ __launch_bounds__(256, 2) void fused_gh_attn(
    const float* __restrict__ node, const float* __restrict__ g,
    const int*  __restrict__ seg,   const float* __restrict__ Wl,
    const float* __restrict__ bl,   int N)
{
    extern __shared__ __align__(16) char sm[];

    if (blockIdx.x < GH_BLOCKS) {
        // gh = g @ Whh^T (3-product sweep), depends only on prep
        uint32_t smem = smem_u32(sm);
        float acc[4][4][4];
        #pragma unroll
        for (int mi = 0; mi < 4; mi++)
            #pragma unroll
            for (int ni = 0; ni < 4; ni++)
                #pragma unroll
                for (int k = 0; k < 4; k++) acc[mi][ni][k] = 0.f;
        int bx = blockIdx.x;
        int m0 = (bx & 31) * 128;
        int j0 = (bx >> 5) * 128;
        run_gemm<12, true>(d_g_hi, d_g_lo, d_whh_hi, d_whh_lo, 0, m0, j0, smem, acc);
        epi_store_raw(g_gh, m0, j0, acc);
        return;
    }

    // ---------------- attention pooling (carves smem from dynamic buffer) ----
    float* wl2      = (float*)sm;                    // 256
    float* red      = wl2 + 256;                     // 256
    float* warp_s   = red + 256;                     // 8
    float* warp_acc = warp_s + 8;                    // 8*256
    int*   bounds   = (int*)(warp_acc + 8*256);      // 2
    float* c1_shp   = (float*)(bounds + 2);          // 1

    int b = blockIdx.x - GH_BLOCKS;
    int t = threadIdx.x, warp = t >> 5, lane = t & 31;

    wl2[t] = Wl[FF + t];
    float gv = g[(size_t)b * FF + t];
    red[t] = fmaxf(gv, 0.f) * Wl[t];

    if (t < 2) {
        int target = b + t, lo = 0, hi = N;
        while (lo < hi) { int mid = (lo + hi) >> 1; if (seg[mid] < target) lo = mid + 1; else hi = mid; }
        bounds[t] = lo;
    }
    __syncthreads();
    for (int s2 = 128; s2 > 0; s2 >>= 1) { if (t < s2) red[t] += red[t + s2]; __syncthreads(); }
    if (t == 0) c1_shp[0] = red[0] + bl[0];
    __syncthreads();

    int start = bounds[0], end = bounds[1];
    if (t == 0) g_cnt[b] = end - start;
    if (end == start) {
        d_s_hi[(size_t)b * FF + t] = __float2bfloat16(0.f);
        d_s_lo[(size_t)b * FF + t] = __float2bfloat16(0.f);
        return;
    }

    float c1 = c1_shp[0];
    float4 A0 = make_float4(0.f,0.f,0.f,0.f), A1 = make_float4(0.f,0.f,0.f,0.f);
    float ssum = 0.f;
    float4 w0 = ((const float4*)wl2)[lane];
    float4 w1 = ((const float4*)wl2)[32 + lane];

    for (int i = start + warp; i < end; i += 16) {
        int  i2  = i + 8;
        bool v2  = i2 < end;
        int  i2s = v2 ? i2 : i;
        const float4* rowA = (const float4*)(node + (size_t)i   * FF);
        const float4* rowB = (const float4*)(node + (size_t)i2s * FF);
        float4 x0 = rowA[lane], x1 = rowA[32 + lane];
        float4 y0 = rowB[lane], y1 = rowB[32 + lane];
        float d1 = x0.x*w0.x + x0.y*w0.y + x0.z*w0.z + x0.w*w0.w
                 + x1.x*w1.x + x1.y*w1.y + x1.z*w1.z + x1.w*w1.w;
        float d2 = y0.x*w0.x + y0.y*w0.y + y0.z*w0.z + y0.w*w0.w
                 + y1.x*w1.x + y1.y*w1.y + y1.z*w1.z + y1.w*w1.w;
        #pragma unroll
        for (int o = 16; o; o >>= 1) {
            d1 += __shfl_xor_sync(0xffffffffu, d1, o);
            d2 += __shfl_xor_sync(0xffffffffu, d2, o);
        }
        float z1 = c1 + d1; z1 = z1 > 0.f ? z1 : 0.01f * z1;
        float z2 = c1 + d2; z2 = z2 > 0.f ? z2 : 0.01f * z2;
        float e1 = __expf(z1);
        float e2 = v2 ? __expf(z2) : 0.f;
        ssum += e1 + e2;
        A0.x += e1*x0.x + e2*y0.x;  A0.y += e1*x0.y + e2*y0.y;
        A0.z += e1*x0.z + e2*y0.z;  A0.w += e1*x0.w + e2*y0.w;
        A1.x += e1*x1.x + e2*y1.x;  A1.y += e1*x1.y + e2*y1.y;
        A1.z += e1*x1.z + e2*y1.z;  A1.w += e1*x1.w + e2*y1.w;
    }
    if (lane == 0) warp_s[warp] = ssum;
    ((float4*)(warp_acc + warp * FF))[lane]      = A0;
    ((float4*)(warp_acc + warp * FF))[32 + lane] = A1;
    __syncthreads();

    float denom = 0.f, val = 0.f;
    #pragma unroll
    for (int w = 0; w < 8; w++) {
        denom += warp_s[w];
        val   += warp_acc[w * FF + t];
    }
    split_store(val / denom, d_s_hi, d_s_lo, (size_t)b * FF + t);
}

// ---------------- ctx GEMM: ctx = elu(s @ Wp^T [+ bp]) -----------------------
__global__ __launch_bounds__(256, 2) void gemm_ctx(const float* __restrict__ bp)
{
    extern __shared__ __align__(16) char sm[];
    uint32_t smem = smem_u32(sm);
    float acc[4][4][4];
    #pragma unroll
    for (int mi = 0; mi < 4; mi++)
        #pragma unroll
        for (int ni = 0; ni < 4; ni++)
            #pragma unroll
            for (int k = 0; k < 4; k++) acc[mi][ni][k] = 0.f;

    int m0 = blockIdx.x * 128, j0 = blockIdx.y * 128;
    run_gemm<12, true>(d_s_hi, d_s_lo, d_wp_hi, d_wp_lo, 0, m0, j0, smem, acc);

    int t = threadIdx.x, wid = t >> 5, lane = t & 31;
    int warp_m = wid & 1, warp_n = wid >> 1;
    int colBase = j0 + warp_n * 32 + (lane & 3) * 2;
    int rowBase = m0 + warp_m * 64 + (lane >> 2);
    #pragma unroll
    for (int mi = 0; mi < 4; mi++)
        #pragma unroll
        for (int ni = 0; ni < 4; ni++) {
            int col = colBase + ni * 8;
            #pragma unroll
            for (int half = 0; half < 2; half++) {
                int row = rowBase + mi * 16 + half * 8;
                float v0 = acc[mi][ni][half*2 + 0];
                float v1 = acc[mi][ni][half*2 + 1];
                if (g_cnt[row] > 0) { v0 += bp[col]; v1 += bp[col + 1]; }
                v0 = v0 > 0.f ? v0 : expm1f(v0);
                v1 = v1 > 0.f ? v1 : expm1f(v1);
                split_store(v0, d_c_hi, d_c_lo, (size_t)row * FF + col);
                split_store(v1, d_c_hi, d_c_lo, (size_t)row * FF + col + 1);
            }
        }
}

// ---------------- gi GEMM, split-K by product term ---------------------------
__global__ __launch_bounds__(256, 2) void gemm_gi()
{
    extern __shared__ __align__(16) char sm[];
    uint32_t smem = smem_u32(sm);
    float acc[4][4][4];
    #pragma unroll
    for (int mi = 0; mi < 4; mi++)
        #pragma unroll
        for (int ni = 0; ni < 4; ni++)
            #pragma unroll
            for (int k = 0; k < 4; k++) acc[mi][ni][k] = 0.f;

    int m0 = blockIdx.x * 128, j0 = blockIdx.y * 128, p = blockIdx.z;
    run_gemm<4, false>(d_c_hi, d_c_lo, d_wih_hi, d_wih_lo, p, m0, j0, smem, acc);
    float* out = (p == 0) ? g_gi0 : (p == 1) ? g_gi1 : g_gi2;
    epi_store_raw(out, m0, j0, acc);
}

// ---------------- GRU combine ------------------------------------------------
__global__ __launch_bounds__(256) void gru_combine(
    const float* __restrict__ gfeats, const float* __restrict__ bih,
    const float* __restrict__ bhh,    float* __restrict__ out)
{
    int b = blockIdx.x, j = threadIdx.x;
    size_t r3 = (size_t)b * (3 * FF);
    float ir  = g_gi0[r3 + j]       + g_gi1[r3 + j]       + g_gi2[r3 + j]       + bih[j];
    float iz  = g_gi0[r3 + 256 + j] + g_gi1[r3 + 256 + j] + g_gi2[r3 + 256 + j] + bih[256 + j];
    float in_ = g_gi0[r3 + 512 + j] + g_gi1[r3 + 512 + j] + g_gi2[r3 + 512 + j] + bih[512 + j];
    float hr  = g_gh[r3 + j]        + bhh[j];
    float hz  = g_gh[r3 + 256 + j]  + bhh[256 + j];
    float hn  = g_gh[r3 + 512 + j]  + bhh[512 + j];
    float r  = 1.f / (1.f + __expf(-(ir + hr)));
    float zg = 1.f / (1.f + __expf(-(iz + hz)));
    float nn = tanhf(in_ + r * hn);
    float gv = gfeats[(size_t)b * FF + j];
    out[(size_t)b * FF + j] = (1.f - zg) * nn + zg * gv;
}

// ---------------- launch ----------------------------------------------------
extern "C" void kernel_launch(void* const* d_in, const int* in_sizes, int n_in,
                              void* d_out, int out_size)
{
    const float* node = (const float*)d_in[0];
    const float* g    = (const float*)d_in[1];
    const int*   seg  = (const int*)  d_in[2];
    const float* Wl   = (const float*)d_in[3];
    const float* bl   = (const float*)d_in[4];
    const float* Wp   = (const float*)d_in[5];
    const float* bp   = (const float*)d_in[6];
    const float* Wih  = (const float*)d_in[7];
    const float* Whh  = (const float*)d_in[8];
    const float* bih  = (const float*)d_in[9];
    const float* bhh  = (const float*)d_in[10];
    float* out = (float*)d_out;
    int N = in_sizes[2];

    cudaFuncSetAttribute(fused_gh_attn, cudaFuncAttributeMaxDynamicSharedMemorySize, GSMEM);
    cudaFuncSetAttribute(gemm_ctx,      cudaFuncAttributeMaxDynamicSharedMemorySize, GSMEM);
    cudaFuncSetAttribute(gemm_gi,       cudaFuncAttributeMaxDynamicSharedMemorySize, GSMEM);

    prep<<<(BB * FF) / 256, 256>>>(Wp, Wih, Whh, g);
    fused_gh_attn<<<GH_BLOCKS + BB, 256, GSMEM>>>(node, g, seg, Wl, bl, N);
    gemm_ctx<<<dim3(32, 2), 256, GSMEM>>>(bp);
    gemm_gi<<<dim3(32, 6, 3), 256, GSMEM>>>();
    gru_combine<<<BB, 256>>>(g, bih, bhh, out);
}

// round 10
// speedup vs baseline: 1.4798x; 1.4798x over previous
#include <cuda_runtime.h>
#include <cuda_bf16.h>
#include <cstdint>
#include <math.h>

#define BB 4096
#define FF 256

// ---------------- scratch (device globals) ----------------------------------
// All GEMM operands stored CHUNK-MAJOR + SWIZZLED:
//   element (row, col) -> slab kc=col>>6, 128B row-chunk, 16B quad
//   q = ((col>>3)&7) ^ (row&7), byte = (col&7)*2
__device__ __nv_bfloat16 d_s_hi[BB*FF],  d_s_lo[BB*FF];
__device__ __nv_bfloat16 d_g_hi[BB*FF],  d_g_lo[BB*FF];
__device__ __nv_bfloat16 d_c_hi[BB*FF],  d_c_lo[BB*FF];
__device__ __nv_bfloat16 d_wp_hi[FF*FF], d_wp_lo[FF*FF];
__device__ __nv_bfloat16 d_wih_hi[3*FF*FF], d_wih_lo[3*FF*FF];
__device__ __nv_bfloat16 d_whh_hi[3*FF*FF], d_whh_lo[3*FF*FF];
__device__ float g_gh[BB*3*FF];
__device__ float g_gi[BB*3*FF];
__device__ int   g_cnt[BB];

// ---------------- helpers ----------------------------------------------------
__device__ __forceinline__ uint32_t smem_u32(const void* p) {
    uint32_t a;
    asm("{ .reg .u64 t; cvta.to.shared.u64 t, %1; cvt.u32.u64 %0, t; }" : "=r"(a) : "l"(p));
    return a;
}
__device__ __forceinline__ void mbar_init(uint32_t a, uint32_t cnt) {
    asm volatile("mbarrier.init.shared.b64 [%0], %1;" :: "r"(a), "r"(cnt) : "memory");
}
__device__ __forceinline__ void mbar_wait(uint32_t a, int parity) {
    asm volatile(
        "{\n\t.reg .pred P;\n\t"
        "LAB_%=:\n\t"
        "mbarrier.try_wait.parity.acquire.cta.shared::cta.b64 P, [%0], %1, 0x989680;\n\t"
        "@!P bra LAB_%=;\n\t}"
        :: "r"(a), "r"((uint32_t)parity) : "memory");
}
__device__ __forceinline__ void ldsm4(uint32_t* r, uint32_t addr) {
    asm volatile("ldmatrix.sync.aligned.m8n8.x4.shared.b16 {%0,%1,%2,%3}, [%4];"
        : "=r"(r[0]), "=r"(r[1]), "=r"(r[2]), "=r"(r[3]) : "r"(addr));
}
__device__ __forceinline__ void mma16816(float* d, const uint32_t* a, uint32_t b0, uint32_t b1) {
    asm volatile("mma.sync.aligned.m16n8k16.row.col.f32.bf16.bf16.f32 "
        "{%0,%1,%2,%3}, {%4,%5,%6,%7}, {%8,%9}, {%0,%1,%2,%3};"
        : "+f"(d[0]), "+f"(d[1]), "+f"(d[2]), "+f"(d[3])
        : "r"(a[0]), "r"(a[1]), "r"(a[2]), "r"(a[3]), "r"(b0), "r"(b1));
}
// swizzled chunk-major index; R = total rows of the matrix
__device__ __forceinline__ size_t sw_idx(int row, int col, int R) {
    int kc = col >> 6;
    int q  = ((col >> 3) & 7) ^ (row & 7);
    return (((size_t)kc * R + row) << 6) + (q << 3) + (col & 7);
}
__device__ __forceinline__ void split_store_sw(float v, __nv_bfloat16* hi, __nv_bfloat16* lo,
                                               int row, int col, int R) {
    size_t i = sw_idx(row, col, R);
    __nv_bfloat16 h = __float2bfloat16(v);
    hi[i] = h;
    lo[i] = __float2bfloat16(v - __bfloat162float(h));
}

// ---------------- kernel P: bf16 hi/lo prep (swizzled layouts) ---------------
__global__ __launch_bounds__(256) void prep(const float* __restrict__ Wp,
                                            const float* __restrict__ Wih,
                                            const float* __restrict__ Whh,
                                            const float* __restrict__ g)
{
    int i = blockIdx.x * 256 + threadIdx.x;
    int row = i >> 8, col = i & 255;
    if (i < FF*FF)      split_store_sw(Wp[i],  d_wp_hi,  d_wp_lo,  row, col, FF);
    if (i < 3*FF*FF) {  split_store_sw(Wih[i], d_wih_hi, d_wih_lo, row, col, 3*FF);
                        split_store_sw(Whh[i], d_whh_hi, d_whh_lo, row, col, 3*FF); }
    if (i < BB*FF)      split_store_sw(g[i],   d_g_hi,   d_g_lo,   row, col, BB);
}

// ---------------- kernel A: per-graph attention pooling (standalone) ---------
__global__ __launch_bounds__(256) void attn_pool(
    const float* __restrict__ node, const float* __restrict__ g,
    const int*  __restrict__ seg,   const float* __restrict__ Wl,
    const float* __restrict__ bl,   int N)
{
    __shared__ float wl2[FF];
    __shared__ float red[256];
    __shared__ float warp_s[8];
    __shared__ float warp_acc[8][FF];
    __shared__ int   bounds[2];
    __shared__ float c1_sh;

    int b = blockIdx.x;
    int t = threadIdx.x, warp = t >> 5, lane = t & 31;

    wl2[t] = Wl[FF + t];
    float gv = g[(size_t)b * FF + t];
    red[t] = fmaxf(gv, 0.f) * Wl[t];

    if (t < 2) {
        int target = b + t, lo = 0, hi = N;
        while (lo < hi) { int mid = (lo + hi) >> 1; if (seg[mid] < target) lo = mid + 1; else hi = mid; }
        bounds[t] = lo;
    }
    __syncthreads();
    for (int s2 = 128; s2 > 0; s2 >>= 1) { if (t < s2) red[t] += red[t + s2]; __syncthreads(); }
    if (t == 0) c1_sh = red[0] + bl[0];
    __syncthreads();

    int start = bounds[0], end = bounds[1];
    if (t == 0) g_cnt[b] = end - start;
    if (end == start) {
        split_store_sw(0.f, d_s_hi, d_s_lo, b, t, BB);
        return;
    }

    float c1 = c1_sh;
    float4 A0 = make_float4(0.f,0.f,0.f,0.f), A1 = make_float4(0.f,0.f,0.f,0.f);
    float ssum = 0.f;
    float4 w0 = ((const float4*)wl2)[lane];
    float4 w1 = ((const float4*)wl2)[32 + lane];

    for (int i = start + warp; i < end; i += 16) {
        int  i2  = i + 8;
        bool v2  = i2 < end;
        int  i2s = v2 ? i2 : i;
        const float4* rowA = (const float4*)(node + (size_t)i   * FF);
        const float4* rowB = (const float4*)(node + (size_t)i2s * FF);
        float4 x0 = rowA[lane], x1 = rowA[32 + lane];
        float4 y0 = rowB[lane], y1 = rowB[32 + lane];
        float d1 = x0.x*w0.x + x0.y*w0.y + x0.z*w0.z + x0.w*w0.w
                 + x1.x*w1.x + x1.y*w1.y + x1.z*w1.z + x1.w*w1.w;
        float d2 = y0.x*w0.x + y0.y*w0.y + y0.z*w0.z + y0.w*w0.w
                 + y1.x*w1.x + y1.y*w1.y + y1.z*w1.z + y1.w*w1.w;
        #pragma unroll
        for (int o = 16; o; o >>= 1) {
            d1 += __shfl_xor_sync(0xffffffffu, d1, o);
            d2 += __shfl_xor_sync(0xffffffffu, d2, o);
        }
        float z1 = c1 + d1; z1 = z1 > 0.f ? z1 : 0.01f * z1;
        float z2 = c1 + d2; z2 = z2 > 0.f ? z2 : 0.01f * z2;
        float e1 = __expf(z1);
        float e2 = v2 ? __expf(z2) : 0.f;
        ssum += e1 + e2;
        A0.x += e1*x0.x + e2*y0.x;  A0.y += e1*x0.y + e2*y0.y;
        A0.z += e1*x0.z + e2*y0.z;  A0.w += e1*x0.w + e2*y0.w;
        A1.x += e1*x1.x + e2*y1.x;  A1.y += e1*x1.y + e2*y1.y;
        A1.z += e1*x1.z + e2*y1.z;  A1.w += e1*x1.w + e2*y1.w;
    }
    if (lane == 0) warp_s[warp] = ssum;
    ((float4*)warp_acc[warp])[lane]      = A0;
    ((float4*)warp_acc[warp])[32 + lane] = A1;
    __syncthreads();

    float denom = 0.f, val = 0.f;
    #pragma unroll
    for (int w = 0; w < 8; w++) {
        denom += warp_s[w];
        val   += warp_acc[w][t];
    }
    split_store_sw(val / denom, d_s_hi, d_s_lo, b, t, BB);
}

// ---------------- kernel G: bulk-DMA fed mma.sync GEMM -----------------------
// Tile 128x128, 8 warps of 64x32, BK=64 chunks, K'=768 sweep (12 chunks).
// Per chunk: 2 x cp.async.bulk of 16KB (A slab, B slab), mbarrier completion.
#define NCHUNK 12
#define NSTAGE 3
#define TILEB  16384
#define STAGE_SZ (2 * TILEB)
#define MBAR_OFF (NSTAGE * STAGE_SZ)       // 98304
#define GSMEM    (MBAR_OFF + 64)

__global__ __launch_bounds__(256, 2) void gemm_bulk(int mode, const float* __restrict__ bp)
{
    extern __shared__ __align__(128) char sm[];
    uint32_t smem = smem_u32(sm);
    uint32_t mbar = smem + MBAR_OFF;

    int t = threadIdx.x, wid = t >> 5, lane = t & 31;
    int warp_m = wid & 1, warp_n = wid >> 1;

    int m0 = blockIdx.x * 128;
    int y  = blockIdx.y;
    const __nv_bfloat16 *Ah, *Al, *Bh, *Bl;
    int j0, oc, RB;
    bool is_ctx = false;
    if (mode == 0) {
        if (y < 2) { Ah=d_s_hi; Al=d_s_lo; Bh=d_wp_hi;  Bl=d_wp_lo;  j0=y*128;     oc=j0; RB=FF;   is_ctx=true; }
        else       { Ah=d_g_hi; Al=d_g_lo; Bh=d_whh_hi; Bl=d_whh_lo; j0=(y-2)*128; oc=j0; RB=3*FF; }
    } else         { Ah=d_c_hi; Al=d_c_lo; Bh=d_wih_hi; Bl=d_wih_lo; j0=y*128;     oc=j0; RB=3*FF; }

    if (t == 0) {
        #pragma unroll
        for (int s = 0; s < NSTAGE; s++) mbar_init(mbar + s * 8, 1);
    }
    __syncthreads();

    auto issue = [&](int cn, int st) {
        if (t != 0) return;
        int p = cn >> 2, kc = cn & 3;
        const __nv_bfloat16* As = (p == 1) ? Al : Ah;
        const __nv_bfloat16* Bs = (p == 2) ? Bl : Bh;
        const __nv_bfloat16* srcA = As + (((size_t)kc * BB + m0) << 6);
        const __nv_bfloat16* srcB = Bs + (((size_t)kc * RB + j0) << 6);
        uint32_t dA = smem + st * STAGE_SZ, dB = dA + TILEB, mb = mbar + st * 8;
        asm volatile("fence.proxy.async.shared::cta;" ::: "memory");
        asm volatile("mbarrier.arrive.expect_tx.shared.b64 _, [%0], %1;"
                     :: "r"(mb), "r"(2u * TILEB) : "memory");
        asm volatile("cp.async.bulk.shared::cluster.global.mbarrier::complete_tx::bytes [%0], [%1], %2, [%3];"
                     :: "r"(dA), "l"(srcA), "r"((uint32_t)TILEB), "r"(mb) : "memory");
        asm volatile("cp.async.bulk.shared::cluster.global.mbarrier::complete_tx::bytes [%0], [%1], %2, [%3];"
                     :: "r"(dB), "l"(srcB), "r"((uint32_t)TILEB), "r"(mb) : "memory");
    };

    float acc[4][4][4];
    #pragma unroll
    for (int mi = 0; mi < 4; mi++)
        #pragma unroll
        for (int ni = 0; ni < 4; ni++)
            #pragma unroll
            for (int k = 0; k < 4; k++) acc[mi][ni][k] = 0.f;

    issue(0, 0); issue(1, 1);

    int aR = warp_m * 64 + (lane & 15);
    int aH = lane >> 4;                 // 0/1 col-half quad
    int bR = warp_n * 32 + lane;

    #pragma unroll 1
    for (int c = 0; c < NCHUNK; c++) {
        int st = c % NSTAGE;
        if (c + 2 < NCHUNK) issue(c + 2, (c + 2) % NSTAGE);
        mbar_wait(mbar + st * 8, (c / NSTAGE) & 1);

        uint32_t bA = smem + st * STAGE_SZ, bB = bA + TILEB;
        #pragma unroll
        for (int ks = 0; ks < 4; ks++) {
            uint32_t a[4][4];
            #pragma unroll
            for (int mi = 0; mi < 4; mi++) {
                int r = aR + mi * 16;
                ldsm4(a[mi], bA + (uint32_t)(r * 128 + (((2*ks + aH) ^ (r & 7)) << 4)));
            }
            uint32_t bb0[4], bb1[4];
            ldsm4(bb0, bB + (uint32_t)(bR * 128 + (((2*ks    ) ^ (bR & 7)) << 4)));
            ldsm4(bb1, bB + (uint32_t)(bR * 128 + (((2*ks + 1) ^ (bR & 7)) << 4)));
            #pragma unroll
            for (int mi = 0; mi < 4; mi++)
                #pragma unroll
                for (int ni = 0; ni < 4; ni++)
                    mma16816(acc[mi][ni], a[mi], bb0[ni], bb1[ni]);
        }
        __syncthreads();               // all warps done with stage st before refill
    }

    // epilogue
    int colBase = warp_n * 32 + (lane & 3) * 2;
    int rowBase = m0 + warp_m * 64 + (lane >> 2);
    float* rawOut = (mode == 0) ? g_gh : g_gi;
    #pragma unroll
    for (int mi = 0; mi < 4; mi++)
        #pragma unroll
        for (int ni = 0; ni < 4; ni++) {
            int col = colBase + ni * 8;
            #pragma unroll
            for (int half = 0; half < 2; half++) {
                int row = rowBase + mi * 16 + half * 8;
                float v0 = acc[mi][ni][half*2 + 0];
                float v1 = acc[mi][ni][half*2 + 1];
                if (is_ctx) {
                    int j = j0 + col;
                    if (g_cnt[row] > 0) { v0 += bp[j]; v1 += bp[j + 1]; }
                    v0 = v0 > 0.f ? v0 : expm1f(v0);
                    v1 = v1 > 0.f ? v1 : expm1f(v1);
                    split_store_sw(v0, d_c_hi, d_c_lo, row, j,     BB);
                    split_store_sw(v1, d_c_hi, d_c_lo, row, j + 1, BB);
                } else {
                    *(float2*)(rawOut + (size_t)row * (3*FF) + oc + col) =
                        make_float2(v0, v1);
                }
            }
        }
}

// ---------------- GRU combine ------------------------------------------------
__global__ __launch_bounds__(256) void gru_combine(
    const float* __restrict__ gfeats, const float* __restrict__ bih,
    const float* __restrict__ bhh,    float* __restrict__ out)
{
    int b = blockIdx.x, j = threadIdx.x;
    size_t r3 = (size_t)b * (3 * FF);
    float ir  = g_gi[r3 + j]        + bih[j];
    float iz  = g_gi[r3 + 256 + j]  + bih[256 + j];
    float in_ = g_gi[r3 + 512 + j]  + bih[512 + j];
    float hr  = g_gh[r3 + j]        + bhh[j];
    float hz  = g_gh[r3 + 256 + j]  + bhh[256 + j];
    float hn  = g_gh[r3 + 512 + j]  + bhh[512 + j];
    float r  = 1.f / (1.f + __expf(-(ir + hr)));
    float zg = 1.f / (1.f + __expf(-(iz + hz)));
    float nn = tanhf(in_ + r * hn);
    float gv = gfeats[(size_t)b * FF + j];
    out[(size_t)b * FF + j] = (1.f - zg) * nn + zg * gv;
}

// ---------------- launch ----------------------------------------------------
extern "C" void kernel_launch(void* const* d_in, const int* in_sizes, int n_in,
                              void* d_out, int out_size)
{
    const float* node = (const float*)d_in[0];
    const float* g    = (const float*)d_in[1];
    const int*   seg  = (const int*)  d_in[2];
    const float* Wl   = (const float*)d_in[3];
    const float* bl   = (const float*)d_in[4];
    const float* Wp   = (const float*)d_in[5];
    const float* bp   = (const float*)d_in[6];
    const float* Wih  = (const float*)d_in[7];
    const float* Whh  = (const float*)d_in[8];
    const float* bih  = (const float*)d_in[9];
    const float* bhh  = (const float*)d_in[10];
    float* out = (float*)d_out;
    int N = in_sizes[2];

    cudaFuncSetAttribute(gemm_bulk, cudaFuncAttributeMaxDynamicSharedMemorySize, GSMEM);

    prep<<<(BB * FF) / 256, 256>>>(Wp, Wih, Whh, g);
    attn_pool<<<BB, 256>>>(node, g, seg, Wl, bl, N);
    gemm_bulk<<<dim3(32, 8), 256, GSMEM>>>(0, bp);   // ctx (y<2) + gh (y>=2)
    gemm_bulk<<<dim3(32, 6), 256, GSMEM>>>(1, bp);   // gi
    gru_combine<<<BB, 256>>>(g, bih, bhh, out);
}

// round 14
// speedup vs baseline: 1.6064x; 1.0855x over previous
#include <cuda_runtime.h>
#include <cuda_bf16.h>
#include <cstdint>
#include <math.h>

#define BB 4096
#define FF 256

// ---------------- scratch (device globals) ----------------------------------
// GEMM operands stored CHUNK-MAJOR + SWIZZLED:
//   (row, col) -> slab kc=col>>6, 128B row-chunk, quad q=((col>>3)&7)^(row&7)
__device__ __nv_bfloat16 d_s_hi[BB*FF],  d_s_lo[BB*FF];
__device__ __nv_bfloat16 d_g_hi[BB*FF],  d_g_lo[BB*FF];
__device__ __nv_bfloat16 d_c_hi[BB*FF],  d_c_lo[BB*FF];
__device__ __nv_bfloat16 d_wp_hi[FF*FF], d_wp_lo[FF*FF];
__device__ __nv_bfloat16 d_wih_hi[3*FF*FF], d_wih_lo[3*FF*FF];
__device__ __nv_bfloat16 d_whh_hi[3*FF*FF], d_whh_lo[3*FF*FF];
__device__ float g_gh [BB*3*FF];
__device__ float g_gi0[BB*3*FF], g_gi1[BB*3*FF];
__device__ int   g_cnt[BB];

// ---------------- helpers ----------------------------------------------------
__device__ __forceinline__ uint32_t smem_u32(const void* p) {
    uint32_t a;
    asm("{ .reg .u64 t; cvta.to.shared.u64 t, %1; cvt.u32.u64 %0, t; }" : "=r"(a) : "l"(p));
    return a;
}
__device__ __forceinline__ void mbar_init(uint32_t a, uint32_t cnt) {
    asm volatile("mbarrier.init.shared.b64 [%0], %1;" :: "r"(a), "r"(cnt) : "memory");
}
__device__ __forceinline__ void mbar_wait(uint32_t a, int parity) {
    asm volatile(
        "{\n\t.reg .pred P;\n\t"
        "LAB_%=:\n\t"
        "mbarrier.try_wait.parity.acquire.cta.shared::cta.b64 P, [%0], %1, 0x989680;\n\t"
        "@!P bra LAB_%=;\n\t}"
        :: "r"(a), "r"((uint32_t)parity) : "memory");
}
__device__ __forceinline__ void ldsm4(uint32_t* r, uint32_t addr) {
    asm volatile("ldmatrix.sync.aligned.m8n8.x4.shared.b16 {%0,%1,%2,%3}, [%4];"
        : "=r"(r[0]), "=r"(r[1]), "=r"(r[2]), "=r"(r[3]) : "r"(addr));
}
__device__ __forceinline__ void mma16816(float* d, const uint32_t* a, uint32_t b0, uint32_t b1) {
    asm volatile("mma.sync.aligned.m16n8k16.row.col.f32.bf16.bf16.f32 "
        "{%0,%1,%2,%3}, {%4,%5,%6,%7}, {%8,%9}, {%0,%1,%2,%3};"
        : "+f"(d[0]), "+f"(d[1]), "+f"(d[2]), "+f"(d[3])
        : "r"(a[0]), "r"(a[1]), "r"(a[2]), "r"(a[3]), "r"(b0), "r"(b1));
}
__device__ __forceinline__ size_t sw_idx(int row, int col, int R) {
    int kc = col >> 6;
    int q  = ((col >> 3) & 7) ^ (row & 7);
    return (((size_t)kc * R + row) << 6) + (q << 3) + (col & 7);
}
__device__ __forceinline__ void split_store_sw(float v, __nv_bfloat16* hi, __nv_bfloat16* lo,
                                               int row, int col, int R) {
    size_t i = sw_idx(row, col, R);
    __nv_bfloat16 h = __float2bfloat16(v);
    hi[i] = h;
    lo[i] = __float2bfloat16(v - __bfloat162float(h));
}

// ---------------- kernel P: bf16 hi/lo prep (swizzled layouts) ---------------
__global__ __launch_bounds__(256) void prep(const float* __restrict__ Wp,
                                            const float* __restrict__ Wih,
                                            const float* __restrict__ Whh,
                                            const float* __restrict__ g)
{
    int i = blockIdx.x * 256 + threadIdx.x;
    int row = i >> 8, col = i & 255;
    if (i < FF*FF)      split_store_sw(Wp[i],  d_wp_hi,  d_wp_lo,  row, col, FF);
    if (i < 3*FF*FF) {  split_store_sw(Wih[i], d_wih_hi, d_wih_lo, row, col, 3*FF);
                        split_store_sw(Whh[i], d_whh_hi, d_whh_lo, row, col, 3*FF); }
    if (i < BB*FF)      split_store_sw(g[i],   d_g_hi,   d_g_lo,   row, col, BB);
}

// ---------------- kernel A: warp-per-graph attention pooling -----------------
// 512 blocks x 8 warps; each warp owns one graph. All dots are warp-reduced,
// so e is uniform across the warp: no block barriers, no cross-warp combine.
__global__ __launch_bounds__(256) void attn_pool(
    const float* __restrict__ node, const float* __restrict__ g,
    const int*  __restrict__ seg,   const float* __restrict__ Wl,
    const float* __restrict__ bl,   int N)
{
    __shared__ float wlA[FF], wlB[FF];
    int t = threadIdx.x, warp = t >> 5, lane = t & 31;
    wlA[t] = Wl[t];
    wlB[t] = Wl[FF + t];
    __syncthreads();

    int b = blockIdx.x * 8 + warp;
    float4 wg0 = ((const float4*)wlA)[lane];
    float4 wg1 = ((const float4*)wlA)[32 + lane];
    float4 w0  = ((const float4*)wlB)[lane];
    float4 w1  = ((const float4*)wlB)[32 + lane];

    // c1 = relu(g_row) . Wl[0:256]
    const float4* grow = (const float4*)(g + (size_t)b * FF);
    float4 gx0 = grow[lane], gx1 = grow[32 + lane];
    float c1p = fmaxf(gx0.x,0.f)*wg0.x + fmaxf(gx0.y,0.f)*wg0.y
              + fmaxf(gx0.z,0.f)*wg0.z + fmaxf(gx0.w,0.f)*wg0.w
              + fmaxf(gx1.x,0.f)*wg1.x + fmaxf(gx1.y,0.f)*wg1.y
              + fmaxf(gx1.z,0.f)*wg1.z + fmaxf(gx1.w,0.f)*wg1.w;
    #pragma unroll
    for (int o = 16; o; o >>= 1) c1p += __shfl_xor_sync(0xffffffffu, c1p, o);

    // segment bounds (lanes 0,1 search; broadcast)
    int lo = 0;
    if (lane < 2) {
        int target = b + lane, hi = N;
        while (lo < hi) { int mid = (lo + hi) >> 1; if (seg[mid] < target) lo = mid + 1; else hi = mid; }
    }
    int start = __shfl_sync(0xffffffffu, lo, 0);
    int end   = __shfl_sync(0xffffffffu, lo, 1);
    if (lane == 0) g_cnt[b] = end - start;

    if (start == end) {
        #pragma unroll
        for (int k = 0; k < 4; k++) {
            split_store_sw(0.f, d_s_hi, d_s_lo, b, 4*lane + k,       BB);
            split_store_sw(0.f, d_s_hi, d_s_lo, b, 128 + 4*lane + k, BB);
        }
        return;
    }

    float c1 = c1p + bl[0];
    float4 A0 = make_float4(0.f,0.f,0.f,0.f), A1 = make_float4(0.f,0.f,0.f,0.f);
    float ssum = 0.f;

    for (int i = start; i < end; i += 2) {
        bool v2 = (i + 1) < end;
        const float4* rA = (const float4*)(node + (size_t)i * FF);
        const float4* rB = (const float4*)(node + (size_t)(v2 ? i + 1 : i) * FF);
        float4 x0 = rA[lane], x1 = rA[32 + lane];
        float4 y0 = rB[lane], y1 = rB[32 + lane];
        float d1 = x0.x*w0.x + x0.y*w0.y + x0.z*w0.z + x0.w*w0.w
                 + x1.x*w1.x + x1.y*w1.y + x1.z*w1.z + x1.w*w1.w;
        float d2 = y0.x*w0.x + y0.y*w0.y + y0.z*w0.z + y0.w*w0.w
                 + y1.x*w1.x + y1.y*w1.y + y1.z*w1.z + y1.w*w1.w;
        #pragma unroll
        for (int o = 16; o; o >>= 1) {
            d1 += __shfl_xor_sync(0xffffffffu, d1, o);
            d2 += __shfl_xor_sync(0xffffffffu, d2, o);
        }
        float z1 = c1 + d1; z1 = z1 > 0.f ? z1 : 0.01f * z1;
        float z2 = c1 + d2; z2 = z2 > 0.f ? z2 : 0.01f * z2;
        float e1 = __expf(z1);
        float e2 = v2 ? __expf(z2) : 0.f;
        ssum += e1 + e2;
        A0.x += e1*x0.x + e2*y0.x;  A0.y += e1*x0.y + e2*y0.y;
        A0.z += e1*x0.z + e2*y0.z;  A0.w += e1*x0.w + e2*y0.w;
        A1.x += e1*x1.x + e2*y1.x;  A1.y += e1*x1.y + e2*y1.y;
        A1.z += e1*x1.z + e2*y1.z;  A1.w += e1*x1.w + e2*y1.w;
    }

    float inv = 1.f / ssum;   // ssum identical on all lanes
    split_store_sw(A0.x*inv, d_s_hi, d_s_lo, b, 4*lane + 0, BB);
    split_store_sw(A0.y*inv, d_s_hi, d_s_lo, b, 4*lane + 1, BB);
    split_store_sw(A0.z*inv, d_s_hi, d_s_lo, b, 4*lane + 2, BB);
    split_store_sw(A0.w*inv, d_s_hi, d_s_lo, b, 4*lane + 3, BB);
    split_store_sw(A1.x*inv, d_s_hi, d_s_lo, b, 128 + 4*lane + 0, BB);
    split_store_sw(A1.y*inv, d_s_hi, d_s_lo, b, 128 + 4*lane + 1, BB);
    split_store_sw(A1.z*inv, d_s_hi, d_s_lo, b, 128 + 4*lane + 2, BB);
    split_store_sw(A1.w*inv, d_s_hi, d_s_lo, b, 128 + 4*lane + 3, BB);
}

// ---------------- bulk-DMA fed mma.sync GEMM core ----------------------------
#define NSTAGE 3
#define TILEB  16384
#define STAGE_SZ (2 * TILEB)
#define MBAR_OFF (NSTAGE * STAGE_SZ)       // 98304
#define GSMEM    (MBAR_OFF + 64)

template<int NCH>
__device__ __forceinline__ void run_bulk(
    const __nv_bfloat16* __restrict__ Ah, const __nv_bfloat16* __restrict__ Al,
    const __nv_bfloat16* __restrict__ Bh, const __nv_bfloat16* __restrict__ Bl,
    int c0, int m0, int j0, int RB, uint32_t smem, float acc[4][4][4])
{
    uint32_t mbar = smem + MBAR_OFF;
    int t = threadIdx.x, wid = t >> 5, lane = t & 31;
    int warp_m = wid & 1, warp_n = wid >> 1;

    if (t == 0) {
        #pragma unroll
        for (int s = 0; s < NSTAGE; s++) mbar_init(mbar + s * 8, 1);
    }
    __syncthreads();

    auto issue = [&](int cn, int st) {
        if (t != 0) return;
        int gc = c0 + cn;
        int p = gc >> 2, kc = gc & 3;
        const __nv_bfloat16* As = (p == 1) ? Al : Ah;
        const __nv_bfloat16* Bs = (p == 2) ? Bl : Bh;
        const __nv_bfloat16* srcA = As + (((size_t)kc * BB + m0) << 6);
        const __nv_bfloat16* srcB = Bs + (((size_t)kc * RB + j0) << 6);
        uint32_t dA = smem + st * STAGE_SZ, dB = dA + TILEB, mb = mbar + st * 8;
        asm volatile("fence.proxy.async.shared::cta;" ::: "memory");
        asm volatile("mbarrier.arrive.expect_tx.shared.b64 _, [%0], %1;"
                     :: "r"(mb), "r"(2u * TILEB) : "memory");
        asm volatile("cp.async.bulk.shared::cluster.global.mbarrier::complete_tx::bytes [%0], [%1], %2, [%3];"
                     :: "r"(dA), "l"(srcA), "r"((uint32_t)TILEB), "r"(mb) : "memory");
        asm volatile("cp.async.bulk.shared::cluster.global.mbarrier::complete_tx::bytes [%0], [%1], %2, [%3];"
                     :: "r"(dB), "l"(srcB), "r"((uint32_t)TILEB), "r"(mb) : "memory");
    };

    issue(0, 0); issue(1, 1);

    int aR = warp_m * 64 + (lane & 15);
    int aH = lane >> 4;
    int bR = warp_n * 32 + lane;

    #pragma unroll 1
    for (int c = 0; c < NCH; c++) {
        int st = c % NSTAGE;
        if (c + 2 < NCH) issue(c + 2, (c + 2) % NSTAGE);
        mbar_wait(mbar + st * 8, (c / NSTAGE) & 1);

        uint32_t bA = smem + st * STAGE_SZ, bB = bA + TILEB;
        #pragma unroll
        for (int ks = 0; ks < 4; ks++) {
            uint32_t a[4][4];
            #pragma unroll
            for (int mi = 0; mi < 4; mi++) {
                int r = aR + mi * 16;
                ldsm4(a[mi], bA + (uint32_t)(r * 128 + (((2*ks + aH) ^ (r & 7)) << 4)));
            }
            uint32_t bb0[4], bb1[4];
            ldsm4(bb0, bB + (uint32_t)(bR * 128 + (((2*ks    ) ^ (bR & 7)) << 4)));
            ldsm4(bb1, bB + (uint32_t)(bR * 128 + (((2*ks + 1) ^ (bR & 7)) << 4)));
            #pragma unroll
            for (int mi = 0; mi < 4; mi++)
                #pragma unroll
                for (int ni = 0; ni < 4; ni++)
                    mma16816(acc[mi][ni], a[mi], bb0[ni], bb1[ni]);
        }
        __syncthreads();
    }
}

__device__ __forceinline__ void epi_store_raw(float* __restrict__ out,
                                              int m0, int j0, float acc[4][4][4])
{
    int t = threadIdx.x, wid = t >> 5, lane = t & 31;
    int warp_m = wid & 1, warp_n = wid >> 1;
    int colBase = warp_n * 32 + (lane & 3) * 2;
    int rowBase = m0 + warp_m * 64 + (lane >> 2);
    #pragma unroll
    for (int mi = 0; mi < 4; mi++)
        #pragma unroll
        for (int ni = 0; ni < 4; ni++) {
            int col = colBase + ni * 8;
            #pragma unroll
            for (int half = 0; half < 2; half++) {
                int row = rowBase + mi * 16 + half * 8;
                *(float2*)(out + (size_t)row * (3*FF) + j0 + col) =
                    make_float2(acc[mi][ni][half*2], acc[mi][ni][half*2+1]);
            }
        }
}

// ---------------- GEMM kernels -----------------------------------------------
__global__ __launch_bounds__(256, 2) void gemm_gh()
{
    extern __shared__ __align__(128) char sm[];
    float acc[4][4][4] = {};
    int m0 = blockIdx.x * 128, j0 = blockIdx.y * 128;
    run_bulk<12>(d_g_hi, d_g_lo, d_whh_hi, d_whh_lo, 0, m0, j0, 3*FF, smem_u32(sm), acc);
    epi_store_raw(g_gh, m0, j0, acc);
}

__global__ __launch_bounds__(256, 2) void gemm_ctx(const float* __restrict__ bp)
{
    extern __shared__ __align__(128) char sm[];
    float acc[4][4][4] = {};
    int m0 = blockIdx.x * 128, j0 = blockIdx.y * 128;
    run_bulk<12>(d_s_hi, d_s_lo, d_wp_hi, d_wp_lo, 0, m0, j0, FF, smem_u32(sm), acc);

    int t = threadIdx.x, wid = t >> 5, lane = t & 31;
    int warp_m = wid & 1, warp_n = wid >> 1;
    int colBase = j0 + warp_n * 32 + (lane & 3) * 2;
    int rowBase = m0 + warp_m * 64 + (lane >> 2);
    #pragma unroll
    for (int mi = 0; mi < 4; mi++)
        #pragma unroll
        for (int ni = 0; ni < 4; ni++) {
            int col = colBase + ni * 8;
            #pragma unroll
            for (int half = 0; half < 2; half++) {
                int row = rowBase + mi * 16 + half * 8;
                float v0 = acc[mi][ni][half*2 + 0];
                float v1 = acc[mi][ni][half*2 + 1];
                if (g_cnt[row] > 0) { v0 += bp[col]; v1 += bp[col + 1]; }
                v0 = v0 > 0.f ? v0 : expm1f(v0);
                v1 = v1 > 0.f ? v1 : expm1f(v1);
                split_store_sw(v0, d_c_hi, d_c_lo, row, col,     BB);
                split_store_sw(v1, d_c_hi, d_c_lo, row, col + 1, BB);
            }
        }
}

__global__ __launch_bounds__(256, 2) void gemm_gi()
{
    extern __shared__ __align__(128) char sm[];
    float acc[4][4][4] = {};
    int m0 = blockIdx.x * 128, j0 = blockIdx.y * 128, z = blockIdx.z;
    run_bulk<6>(d_c_hi, d_c_lo, d_wih_hi, d_wih_lo, z * 6, m0, j0, 3*FF, smem_u32(sm), acc);
    epi_store_raw(z == 0 ? g_gi0 : g_gi1, m0, j0, acc);
}

// ---------------- GRU combine ------------------------------------------------
__global__ __launch_bounds__(256) void gru_combine(
    const float* __restrict__ gfeats, const float* __restrict__ bih,
    const float* __restrict__ bhh,    float* __restrict__ out)
{
    int b = blockIdx.x, j = threadIdx.x;
    size_t r3 = (size_t)b * (3 * FF);
    float ir  = g_gi0[r3 + j]       + g_gi1[r3 + j]       + bih[j];
    float iz  = g_gi0[r3 + 256 + j] + g_gi1[r3 + 256 + j] + bih[256 + j];
    float in_ = g_gi0[r3 + 512 + j] + g_gi1[r3 + 512 + j] + bih[512 + j];
    float hr  = g_gh[r3 + j]        + bhh[j];
    float hz  = g_gh[r3 + 256 + j]  + bhh[256 + j];
    float hn  = g_gh[r3 + 512 + j]  + bhh[512 + j];
    float r  = 1.f / (1.f + __expf(-(ir + hr)));
    float zg = 1.f / (1.f + __expf(-(iz + hz)));
    float nn = tanhf(in_ + r * hn);
    float gv = gfeats[(size_t)b * FF + j];
    out[(size_t)b * FF + j] = (1.f - zg) * nn + zg * gv;
}

// ---------------- launch ----------------------------------------------------
extern "C" void kernel_launch(void* const* d_in, const int* in_sizes, int n_in,
                              void* d_out, int out_size)
{
    const float* node = (const float*)d_in[0];
    const float* g    = (const float*)d_in[1];
    const int*   seg  = (const int*)  d_in[2];
    const float* Wl   = (const float*)d_in[3];
    const float* bl   = (const float*)d_in[4];
    const float* Wp   = (const float*)d_in[5];
    const float* bp   = (const float*)d_in[6];
    const float* Wih  = (const float*)d_in[7];
    const float* Whh  = (const float*)d_in[8];
    const float* bih  = (const float*)d_in[9];
    const float* bhh  = (const float*)d_in[10];
    float* out = (float*)d_out;
    int N = in_sizes[2];

    static int inited = 0;
    static cudaStream_t s_fork = 0;
    static cudaEvent_t evA = 0, evB = 0;
    if (!inited) {
        if (cudaStreamCreateWithFlags(&s_fork, cudaStreamNonBlocking) != cudaSuccess) s_fork = 0;
        cudaEventCreateWithFlags(&evA, cudaEventDisableTiming);
        cudaEventCreateWithFlags(&evB, cudaEventDisableTiming);
        inited = 1;
    }

    cudaFuncSetAttribute(gemm_gh,  cudaFuncAttributeMaxDynamicSharedMemorySize, GSMEM);
    cudaFuncSetAttribute(gemm_ctx, cudaFuncAttributeMaxDynamicSharedMemorySize, GSMEM);
    cudaFuncSetAttribute(gemm_gi,  cudaFuncAttributeMaxDynamicSharedMemorySize, GSMEM);

    prep<<<(BB * FF) / 256, 256>>>(Wp, Wih, Whh, g);

    // fork: gh depends only on prep; overlap it with attention
    cudaEventRecord(evA, 0);
    cudaStreamWaitEvent(s_fork, evA, 0);
    gemm_gh<<<dim3(32, 6), 256, GSMEM, s_fork>>>();
    cudaEventRecord(evB, s_fork);

    attn_pool<<<BB / 8, 256>>>(node, g, seg, Wl, bl, N);
    gemm_ctx<<<dim3(32, 2), 256, GSMEM>>>(bp);
    gemm_gi<<<dim3(32, 6, 2), 256, GSMEM>>>();

    // join before the combine
    cudaStreamWaitEvent(0, evB, 0);
    gru_combine<<<BB, 256>>>(g, bih, bhh, out);
}